// round 11
// baseline (speedup 1.0000x reference)
#include <cuda_runtime.h>

#define BATCH 64
#define IMG_H 1024
#define IMG_W 1024
#define NPTS  256
#define MAX_ITERS 20
#define TOTAL (BATCH * NPTS)

// Device scratch (no allocations allowed)
__device__ int2 g_end[TOTAL];
__device__ int  g_cnt[TOTAL];
__device__ int  g_leader[TOTAL];
__device__ int  g_winner[TOTAL];

// Order-preserving float->uint map (total order, matches float > on non-NaN)
__device__ __forceinline__ unsigned ordkey(float f) {
    unsigned u = __float_as_uint(f);
    return (u & 0x80000000u) ? ~u : (u | 0x80000000u);
}

// ---------------------------------------------------------------------------
// Kernel 1: fused smooth + gravity_move — one warp per point.
// R4 code shape (32 regs) + 128-thread blocks + occupancy pinned via
// __launch_bounds__(128,16): latency-chain-bound kernel, resident warps are
// the lever. argmax over 7x7 candidates of smoothed depth == argmax of raw
// 3x3 box sums. REDUX argmax: max ordkey then min candidate index among
// maxima == jnp.argmax first-occurrence (clamped duplicates bitwise-equal).
// Per-point fixed-point iteration == reference global while_loop (validated).
// ---------------------------------------------------------------------------
__global__ __launch_bounds__(128, 16)
void gravity_kernel(const float* __restrict__ depth,
                    const int*   __restrict__ points)
{
    __shared__ float swin[4][84];   // 81 + pad, per warp
    const int warp = threadIdx.x >> 5;
    const int lane = threadIdx.x & 31;
    const int p = (blockIdx.x << 2) + warp;       // grid = TOTAL/4 exactly
    const int b = p >> 8;
    const float* img = depth + (size_t)b * (IMG_H * IMG_W);
    float* w = swin[warp];

    int x = points[p * 2 + 0];
    int y = points[p * 2 + 1];

    // per-lane constants
    const int er0 = lane / 9,        ec0 = lane % 9;
    const int er1 = (lane + 32) / 9, ec1 = (lane + 32) % 9;
    const int er2 = (lane + 64) / 9, ec2 = (lane + 64) % 9;   // lanes < 17
    const int k1  = lane;      const int d1y = k1 / 7 - 3, d1x = k1 % 7 - 3;
    const int k2  = lane + 32; const int d2y = k2 / 7 - 3, d2x = k2 % 7 - 3;

    for (int it = 0; it < MAX_ITERS; ++it) {
        const int by0 = y - 4, bx0 = x - 4;
        const float* base = img + by0 * IMG_W + bx0;
        // warp-uniform branch: unpredicated loads for interior (common case)
        if (x >= 4 && x <= IMG_W - 5 && y >= 4 && y <= IMG_H - 5) {
            w[lane]      = __ldg(base + er0 * IMG_W + ec0);
            w[lane + 32] = __ldg(base + er1 * IMG_W + ec1);
            if (lane < 17)
                w[lane + 64] = __ldg(base + er2 * IMG_W + ec2);
        } else {
            int ry = by0 + er0, rx = bx0 + ec0;
            w[lane] = (ry >= 0 && ry < IMG_H && rx >= 0 && rx < IMG_W)
                        ? __ldg(img + ry * IMG_W + rx) : 0.0f;
            ry = by0 + er1; rx = bx0 + ec1;
            w[lane + 32] = (ry >= 0 && ry < IMG_H && rx >= 0 && rx < IMG_W)
                        ? __ldg(img + ry * IMG_W + rx) : 0.0f;
            if (lane < 17) {
                ry = by0 + er2; rx = bx0 + ec2;
                w[lane + 64] = (ry >= 0 && ry < IMG_H && rx >= 0 && rx < IMG_W)
                        ? __ldg(img + ry * IMG_W + rx) : 0.0f;
            }
        }
        __syncwarp();

        // candidate 1 (all lanes)
        unsigned ub; int bk;
        {
            int cy = min(max(y + d1y, 0), IMG_H - 1);
            int cx = min(max(x + d1x, 0), IMG_W - 1);
            const float* q = w + (cy - by0) * 9 + (cx - bx0);
            float s = q[-10] + q[-9] + q[-8]
                    + q[-1]  + q[0]  + q[1]
                    + q[8]   + q[9]  + q[10];
            ub = ordkey(s); bk = k1;
        }
        // candidate 2 (lanes < 17)
        if (lane < 17) {
            int cy = min(max(y + d2y, 0), IMG_H - 1);
            int cx = min(max(x + d2x, 0), IMG_W - 1);
            const float* q = w + (cy - by0) * 9 + (cx - bx0);
            float s = q[-10] + q[-9] + q[-8]
                    + q[-1]  + q[0]  + q[1]
                    + q[8]   + q[9]  + q[10];
            unsigned u2 = ordkey(s);
            if (u2 > ub) { ub = u2; bk = k2; }   // tie keeps smaller k1
        }

        // warp argmax: max key, then min index among maxima
        unsigned umax = __reduce_max_sync(0xffffffffu, ub);
        int bkg = (int)__reduce_min_sync(0xffffffffu,
                        (ub == umax) ? (unsigned)bk : 64u);

        int ny = min(max(y + bkg / 7 - 3, 0), IMG_H - 1);
        int nx = min(max(x + bkg % 7 - 3, 0), IMG_W - 1);
        __syncwarp();                  // protect smem before next-iter writes
        if (nx == x && ny == y) break; // warp-uniform
        x = nx; y = ny;
    }

    if (lane == 0) g_end[p] = make_int2(x, y);
}

// ---------------------------------------------------------------------------
// Kernel 2: pairwise overlap stats — full-chip spread + SIMD halfword math.
// grid = BATCH*4 (256 blocks), block = 512: 64 points/block, 8 threads/point
// scanning 32 j's from smem. Coords packed (y<<16)|x; on int coords
// distSq<4 <=> Chebyshev<=1 (one __vabsdiffu2 + mask). Partial (cnt, min
// leader, lexmin (startD2,j) winner) merged over aligned 8-lane octet.
// ---------------------------------------------------------------------------
__global__ __launch_bounds__(512)
void pairs_kernel(const int* __restrict__ points)
{
    __shared__ int sE[NPTS], sS[NPTS];
    const int b = blockIdx.x >> 2;
    const int chunk = blockIdx.x & 3;
    const int t = threadIdx.x;
    if (t < NPTS) {
        int gi = b * NPTS + t;
        int2 e = g_end[gi];
        sE[t] = e.x | (e.y << 16);
        sS[t] = points[gi * 2 + 0] | (points[gi * 2 + 1] << 16);
    }
    __syncthreads();

    const int i   = chunk * 64 + (t >> 3);
    const int sub = t & 7;
    const int ei = sE[i];
    const int ex = ei & 0xFFFF, ey = ei >> 16;

    int cnt = 0, leader = NPTS, winner = NPTS, bestd2 = 0x7fffffff;
    const int j0 = sub * 32;
    #pragma unroll 8
    for (int jj = 0; jj < 32; ++jj) {
        int j = j0 + jj;
        unsigned d = __vabsdiffu2((unsigned)ei, (unsigned)sE[j]);
        if ((d & 0xFFFEFFFEu) == 0u) {        // both |dx|,|dy| <= 1
            cnt++;
            leader = min(leader, j);
            int sj = sS[j];
            int ax = (sj & 0xFFFF) - ex, ay = (sj >> 16) - ey;
            int d2 = ax * ax + ay * ay;
            if (d2 < bestd2 || (d2 == bestd2 && j < winner)) {
                bestd2 = d2; winner = j;
            }
        }
    }
    #pragma unroll
    for (int off = 4; off; off >>= 1) {
        int oc = __shfl_down_sync(0xffffffffu, cnt,    off);
        int ol = __shfl_down_sync(0xffffffffu, leader, off);
        int od = __shfl_down_sync(0xffffffffu, bestd2, off);
        int ow = __shfl_down_sync(0xffffffffu, winner, off);
        cnt += oc;
        leader = min(leader, ol);
        if (od < bestd2 || (od == bestd2 && ow < winner)) {
            bestd2 = od; winner = ow;
        }
    }
    if (sub == 0) {
        int gi = b * NPTS + i;
        g_cnt[gi] = cnt; g_leader[gi] = leader; g_winner[gi] = winner;
    }
}

// ---------------------------------------------------------------------------
// Kernel 3: finalize — win[leader] resolution, peak, output write.
// Output layout (f32): [end(B,N,2) | peak(B,N)].
// ---------------------------------------------------------------------------
__global__ __launch_bounds__(128)
void finalize_kernel(const float* __restrict__ depth,
                     const int*   __restrict__ points,
                     float*       __restrict__ out,
                     int out_size)
{
    const int gi = blockIdx.x * 128 + threadIdx.x;
    const int b  = gi >> 8;
    const int i  = gi & 255;

    int outx, outy;
    int2 e = g_end[gi];
    if (g_cnt[gi] > 1) {
        int leader = g_leader[gi];
        if (i == g_winner[b * NPTS + leader]) {
            int2 el = g_end[b * NPTS + leader];
            outx = el.x; outy = el.y;
        } else {
            outx = points[gi * 2 + 0];
            outy = points[gi * 2 + 1];
        }
    } else {
        outx = e.x; outy = e.y;
    }

    const float* img = depth + (size_t)b * (IMG_H * IMG_W);
    float s = 0.0f;
    #pragma unroll
    for (int di = -1; di <= 1; ++di)
        #pragma unroll
        for (int dj = -1; dj <= 1; ++dj) {
            int ry = outy + di, rx = outx + dj;
            if (ry >= 0 && ry < IMG_H && rx >= 0 && rx < IMG_W)
                s += __ldg(img + ry * IMG_W + rx);
        }

    out[gi * 2 + 0] = (float)outx;
    out[gi * 2 + 1] = (float)outy;
    if (out_size >= TOTAL * 3)
        out[TOTAL * 2 + gi] = s * (1.0f / 9.0f);
}

// ---------------------------------------------------------------------------
extern "C" void kernel_launch(void* const* d_in, const int* in_sizes, int n_in,
                              void* d_out, int out_size)
{
    const float* depth;
    const int*   points;
    if (in_sizes[0] > in_sizes[1]) {
        depth  = (const float*)d_in[0];
        points = (const int*)  d_in[1];
    } else {
        depth  = (const float*)d_in[1];
        points = (const int*)  d_in[0];
    }
    float* out = (float*)d_out;

    gravity_kernel <<<TOTAL / 4, 128>>>(depth, points);
    pairs_kernel   <<<BATCH * 4, 512>>>(points);
    finalize_kernel<<<TOTAL / 128, 128>>>(depth, points, out, out_size);
}

// round 13
// speedup vs baseline: 1.4751x; 1.4751x over previous
#include <cuda_runtime.h>

#define BATCH 64
#define IMG_H 1024
#define IMG_W 1024
#define NPTS  256
#define MAX_ITERS 20
#define TOTAL (BATCH * NPTS)

// Device scratch (no allocations allowed)
__device__ int2 g_end[TOTAL];
__device__ int  g_cnt[TOTAL];
__device__ int  g_leader[TOTAL];
__device__ int  g_winner[TOTAL];

// Order-preserving float->uint map (total order, matches float > on non-NaN)
__device__ __forceinline__ unsigned ordkey(float f) {
    unsigned u = __float_as_uint(f);
    return (u & 0x80000000u) ? ~u : (u | 0x80000000u);
}

// ---------------------------------------------------------------------------
// Kernel 1: fused smooth + gravity_move — one warp per point.
// EXACT Round-4-proposal shape: 256-thread blocks, grid TOTAL/8, inline
// per-iteration addressing (32 regs), REDUX argmax. This configuration
// measured best (~11.4us). argmax over 7x7 candidates of smoothed depth ==
// argmax of raw 3x3 box sums; REDUX max-ordkey then min candidate index
// among maxima == jnp.argmax first-occurrence (clamped duplicate candidates
// are bitwise-equal so min-index is exact). Per-point fixed-point iteration
// == reference global while_loop (validated since R3).
// ---------------------------------------------------------------------------
__global__ __launch_bounds__(256)
void gravity_kernel(const float* __restrict__ depth,
                    const int*   __restrict__ points)
{
    __shared__ float swin[8][84];   // 81 + pad
    const int warp = threadIdx.x >> 5;
    const int lane = threadIdx.x & 31;
    const int p = (blockIdx.x << 3) + warp;       // grid = TOTAL/8 exactly
    const int b = p >> 8;
    const float* img = depth + (size_t)b * (IMG_H * IMG_W);
    float* w = swin[warp];

    int x = points[p * 2 + 0];
    int y = points[p * 2 + 1];

    // per-lane constants
    const int er0 = lane / 9,        ec0 = lane % 9;
    const int er1 = (lane + 32) / 9, ec1 = (lane + 32) % 9;
    const int er2 = (lane + 64) / 9, ec2 = (lane + 64) % 9;   // lanes < 17
    const int k1  = lane;      const int d1y = k1 / 7 - 3, d1x = k1 % 7 - 3;
    const int k2  = lane + 32; const int d2y = k2 / 7 - 3, d2x = k2 % 7 - 3;

    for (int it = 0; it < MAX_ITERS; ++it) {
        const int by0 = y - 4, bx0 = x - 4;
        const float* base = img + by0 * IMG_W + bx0;
        // warp-uniform branch: unpredicated loads for interior (common case)
        if (x >= 4 && x <= IMG_W - 5 && y >= 4 && y <= IMG_H - 5) {
            w[lane]      = __ldg(base + er0 * IMG_W + ec0);
            w[lane + 32] = __ldg(base + er1 * IMG_W + ec1);
            if (lane < 17)
                w[lane + 64] = __ldg(base + er2 * IMG_W + ec2);
        } else {
            int ry = by0 + er0, rx = bx0 + ec0;
            w[lane] = (ry >= 0 && ry < IMG_H && rx >= 0 && rx < IMG_W)
                        ? __ldg(img + ry * IMG_W + rx) : 0.0f;
            ry = by0 + er1; rx = bx0 + ec1;
            w[lane + 32] = (ry >= 0 && ry < IMG_H && rx >= 0 && rx < IMG_W)
                        ? __ldg(img + ry * IMG_W + rx) : 0.0f;
            if (lane < 17) {
                ry = by0 + er2; rx = bx0 + ec2;
                w[lane + 64] = (ry >= 0 && ry < IMG_H && rx >= 0 && rx < IMG_W)
                        ? __ldg(img + ry * IMG_W + rx) : 0.0f;
            }
        }
        __syncwarp();

        // candidate 1 (all lanes)
        unsigned ub; int bk;
        {
            int cy = min(max(y + d1y, 0), IMG_H - 1);
            int cx = min(max(x + d1x, 0), IMG_W - 1);
            const float* q = w + (cy - by0) * 9 + (cx - bx0);
            float s = q[-10] + q[-9] + q[-8]
                    + q[-1]  + q[0]  + q[1]
                    + q[8]   + q[9]  + q[10];
            ub = ordkey(s); bk = k1;
        }
        // candidate 2 (lanes < 17)
        if (lane < 17) {
            int cy = min(max(y + d2y, 0), IMG_H - 1);
            int cx = min(max(x + d2x, 0), IMG_W - 1);
            const float* q = w + (cy - by0) * 9 + (cx - bx0);
            float s = q[-10] + q[-9] + q[-8]
                    + q[-1]  + q[0]  + q[1]
                    + q[8]   + q[9]  + q[10];
            unsigned u2 = ordkey(s);
            if (u2 > ub) { ub = u2; bk = k2; }   // tie keeps smaller k1
        }

        // warp argmax: max key, then min index among maxima
        unsigned umax = __reduce_max_sync(0xffffffffu, ub);
        int bkg = (int)__reduce_min_sync(0xffffffffu,
                        (ub == umax) ? (unsigned)bk : 64u);

        int ny = min(max(y + bkg / 7 - 3, 0), IMG_H - 1);
        int nx = min(max(x + bkg % 7 - 3, 0), IMG_W - 1);
        __syncwarp();                  // protect smem before next-iter writes
        if (nx == x && ny == y) break; // warp-uniform
        x = nx; y = ny;
    }

    if (lane == 0) g_end[p] = make_int2(x, y);
}

// ---------------------------------------------------------------------------
// Kernel 2: pairwise overlap stats — full-chip spread + SIMD halfword math.
// grid = BATCH*4 (256 blocks), block = 512: 64 points/block, 8 threads/point
// scanning 32 j's from smem. Coords packed (y<<16)|x; on int coords
// distSq<4 <=> Chebyshev<=1 (one __vabsdiffu2 + mask). Partial (cnt, min
// leader, lexmin (startD2,j) winner) merged over aligned 8-lane octet.
// ---------------------------------------------------------------------------
__global__ __launch_bounds__(512)
void pairs_kernel(const int* __restrict__ points)
{
    __shared__ int sE[NPTS], sS[NPTS];
    const int b = blockIdx.x >> 2;
    const int chunk = blockIdx.x & 3;
    const int t = threadIdx.x;
    if (t < NPTS) {
        int gi = b * NPTS + t;
        int2 e = g_end[gi];
        sE[t] = e.x | (e.y << 16);
        sS[t] = points[gi * 2 + 0] | (points[gi * 2 + 1] << 16);
    }
    __syncthreads();

    const int i   = chunk * 64 + (t >> 3);
    const int sub = t & 7;
    const int ei = sE[i];
    const int ex = ei & 0xFFFF, ey = ei >> 16;

    int cnt = 0, leader = NPTS, winner = NPTS, bestd2 = 0x7fffffff;
    const int j0 = sub * 32;
    #pragma unroll 8
    for (int jj = 0; jj < 32; ++jj) {
        int j = j0 + jj;
        unsigned d = __vabsdiffu2((unsigned)ei, (unsigned)sE[j]);
        if ((d & 0xFFFEFFFEu) == 0u) {        // both |dx|,|dy| <= 1
            cnt++;
            leader = min(leader, j);
            int sj = sS[j];
            int ax = (sj & 0xFFFF) - ex, ay = (sj >> 16) - ey;
            int d2 = ax * ax + ay * ay;
            if (d2 < bestd2 || (d2 == bestd2 && j < winner)) {
                bestd2 = d2; winner = j;
            }
        }
    }
    #pragma unroll
    for (int off = 4; off; off >>= 1) {
        int oc = __shfl_down_sync(0xffffffffu, cnt,    off);
        int ol = __shfl_down_sync(0xffffffffu, leader, off);
        int od = __shfl_down_sync(0xffffffffu, bestd2, off);
        int ow = __shfl_down_sync(0xffffffffu, winner, off);
        cnt += oc;
        leader = min(leader, ol);
        if (od < bestd2 || (od == bestd2 && ow < winner)) {
            bestd2 = od; winner = ow;
        }
    }
    if (sub == 0) {
        int gi = b * NPTS + i;
        g_cnt[gi] = cnt; g_leader[gi] = leader; g_winner[gi] = winner;
    }
}

// ---------------------------------------------------------------------------
// Kernel 3: finalize — win[leader] resolution, peak, output write.
// Output layout (f32): [end(B,N,2) | peak(B,N)].
// ---------------------------------------------------------------------------
__global__ __launch_bounds__(128)
void finalize_kernel(const float* __restrict__ depth,
                     const int*   __restrict__ points,
                     float*       __restrict__ out,
                     int out_size)
{
    const int gi = blockIdx.x * 128 + threadIdx.x;
    const int b  = gi >> 8;
    const int i  = gi & 255;

    int outx, outy;
    int2 e = g_end[gi];
    if (g_cnt[gi] > 1) {
        int leader = g_leader[gi];
        if (i == g_winner[b * NPTS + leader]) {
            int2 el = g_end[b * NPTS + leader];
            outx = el.x; outy = el.y;
        } else {
            outx = points[gi * 2 + 0];
            outy = points[gi * 2 + 1];
        }
    } else {
        outx = e.x; outy = e.y;
    }

    const float* img = depth + (size_t)b * (IMG_H * IMG_W);
    float s = 0.0f;
    #pragma unroll
    for (int di = -1; di <= 1; ++di)
        #pragma unroll
        for (int dj = -1; dj <= 1; ++dj) {
            int ry = outy + di, rx = outx + dj;
            if (ry >= 0 && ry < IMG_H && rx >= 0 && rx < IMG_W)
                s += __ldg(img + ry * IMG_W + rx);
        }

    out[gi * 2 + 0] = (float)outx;
    out[gi * 2 + 1] = (float)outy;
    if (out_size >= TOTAL * 3)
        out[TOTAL * 2 + gi] = s * (1.0f / 9.0f);
}

// ---------------------------------------------------------------------------
extern "C" void kernel_launch(void* const* d_in, const int* in_sizes, int n_in,
                              void* d_out, int out_size)
{
    const float* depth;
    const int*   points;
    if (in_sizes[0] > in_sizes[1]) {
        depth  = (const float*)d_in[0];
        points = (const int*)  d_in[1];
    } else {
        depth  = (const float*)d_in[1];
        points = (const int*)  d_in[0];
    }
    float* out = (float*)d_out;

    gravity_kernel <<<TOTAL / 8, 256>>>(depth, points);
    pairs_kernel   <<<BATCH * 4, 512>>>(points);
    finalize_kernel<<<TOTAL / 128, 128>>>(depth, points, out, out_size);
}